// round 5
// baseline (speedup 1.0000x reference)
#include <cuda_runtime.h>
#include <cuda_bf16.h>

#define BB 4
#define SS 2048
#define EE 1024

typedef __nv_bfloat16 bf16;

// ---------------------------------------------------------------------------
// Scratch (device globals — no allocation allowed)
// ---------------------------------------------------------------------------
__device__ float g_sc[(size_t)BB * SS * SS];
__device__ float g_m[BB * SS], g_inv[BB * SS];
__device__ bf16 g_xh[(size_t)BB * SS * EE], g_xl[(size_t)BB * SS * EE];
__device__ bf16 g_Wh[3 * (size_t)EE * EE], g_Wl[3 * (size_t)EE * EE];
__device__ bf16 g_qh[(size_t)BB * SS * EE], g_ql[(size_t)BB * SS * EE];
__device__ bf16 g_kh[(size_t)BB * SS * EE], g_kl[(size_t)BB * SS * EE];
__device__ bf16 g_vh[(size_t)BB * SS * EE], g_vl[(size_t)BB * SS * EE];
__device__ bf16 g_vTh[(size_t)BB * EE * SS], g_vTl[(size_t)BB * EE * SS];

// ---------------------------------------------------------------------------
// PTX helpers (baseline sm_80+ features only — plain sm_103 target)
// ---------------------------------------------------------------------------
__device__ __forceinline__ unsigned smem_u32(const void* p) {
    unsigned a;
    asm("{ .reg .u64 t; cvta.to.shared.u64 t, %1; cvt.u32.u64 %0, t; }"
        : "=r"(a) : "l"(p));
    return a;
}
__device__ __forceinline__ void cp16(unsigned dst, const void* src) {
    asm volatile("cp.async.cg.shared.global [%0], [%1], 16;"
                 :: "r"(dst), "l"(src) : "memory");
}
__device__ __forceinline__ void cp_commit() {
    asm volatile("cp.async.commit_group;" ::: "memory");
}
__device__ __forceinline__ void cp_wait1() {
    asm volatile("cp.async.wait_group 1;" ::: "memory");
}
__device__ __forceinline__ void cp_wait0() {
    asm volatile("cp.async.wait_group 0;" ::: "memory");
}
__device__ __forceinline__ void ldsm4(unsigned& r0, unsigned& r1, unsigned& r2,
                                      unsigned& r3, unsigned addr) {
    asm volatile("ldmatrix.sync.aligned.m8n8.x4.shared.b16 {%0,%1,%2,%3}, [%4];"
                 : "=r"(r0), "=r"(r1), "=r"(r2), "=r"(r3) : "r"(addr));
}
__device__ __forceinline__ void mma16816(float* d, const unsigned* a,
                                         unsigned b0, unsigned b1) {
    asm volatile(
        "mma.sync.aligned.m16n8k16.row.col.f32.bf16.bf16.f32 "
        "{%0,%1,%2,%3}, {%4,%5,%6,%7}, {%8,%9}, {%0,%1,%2,%3};"
        : "+f"(d[0]), "+f"(d[1]), "+f"(d[2]), "+f"(d[3])
        : "r"(a[0]), "r"(a[1]), "r"(a[2]), "r"(a[3]), "r"(b0), "r"(b1));
}

// ---------------------------------------------------------------------------
// Tile layout: per buffer 4 tiles [Ah, Al, Bh, Bl], each 128 rows x 32 bf16
// (rows padded to 40 bf16 = 80B). 3 pipeline stages.
// ---------------------------------------------------------------------------
#define ROWPAD 40
#define ROWB   (ROWPAD * 2)
#define TILE_B (128 * ROWB)                 // 10240 bytes
#define NSTAGE 3
#define SMEM_BYTES (NSTAGE * 4 * TILE_B)    // 122880 bytes

// 3-pass compute on one buffered k-tile: acc += Ah*Bh + Al*Bh + Ah*Bl
__device__ __forceinline__ void compute_tiles(unsigned smBase, int buf,
                                              int wm, int wn, int lrow, int lk,
                                              float acc[2][8][4])
{
    const unsigned tb = smBase + buf * (4 * TILE_B);
    #pragma unroll
    for (int ks = 0; ks < 2; ks++) {
        unsigned ah[2][4], al[2][4], bh[4][4], bl[4][4];
        #pragma unroll
        for (int mi = 0; mi < 2; mi++) {
            unsigned off = (wm * 32 + mi * 16 + lrow) * ROWB + ks * 32 + lk;
            ldsm4(ah[mi][0], ah[mi][1], ah[mi][2], ah[mi][3], tb + 0 * TILE_B + off);
            ldsm4(al[mi][0], al[mi][1], al[mi][2], al[mi][3], tb + 1 * TILE_B + off);
        }
        #pragma unroll
        for (int nj = 0; nj < 4; nj++) {
            unsigned off = (wn * 64 + nj * 16 + lrow) * ROWB + ks * 32 + lk;
            ldsm4(bh[nj][0], bh[nj][1], bh[nj][2], bh[nj][3], tb + 2 * TILE_B + off);
            ldsm4(bl[nj][0], bl[nj][1], bl[nj][2], bl[nj][3], tb + 3 * TILE_B + off);
        }
        #pragma unroll
        for (int mi = 0; mi < 2; mi++)
            #pragma unroll
            for (int nj = 0; nj < 4; nj++) {
                mma16816(acc[mi][2 * nj],     ah[mi], bh[nj][0], bh[nj][2]);
                mma16816(acc[mi][2 * nj + 1], ah[mi], bh[nj][1], bh[nj][3]);
                mma16816(acc[mi][2 * nj],     al[mi], bh[nj][0], bh[nj][2]);
                mma16816(acc[mi][2 * nj + 1], al[mi], bh[nj][1], bh[nj][3]);
                mma16816(acc[mi][2 * nj],     ah[mi], bl[nj][0], bl[nj][2]);
                mma16816(acc[mi][2 * nj + 1], ah[mi], bl[nj][1], bl[nj][3]);
            }
    }
}

// cp.async loader for all 4 bf16 tiles
__device__ __forceinline__ void load_tiles4(unsigned smBase, int buf,
    const bf16* Ah, const bf16* Al, int lda,
    const bf16* Bh, const bf16* Bl, int ldb,
    int rowBase, int colBase, int kt, int tid)
{
    const unsigned dstb = smBase + buf * (4 * TILE_B);
    const char* srcA_h = (const char*)(Ah + (size_t)rowBase * lda + kt);
    const char* srcA_l = (const char*)(Al + (size_t)rowBase * lda + kt);
    const char* srcB_h = (const char*)(Bh + (size_t)colBase * ldb + kt);
    const char* srcB_l = (const char*)(Bl + (size_t)colBase * ldb + kt);
    const size_t strA = (size_t)lda * 2, strB = (size_t)ldb * 2;
    #pragma unroll
    for (int i = 0; i < 8; i++) {
        const int tile = i >> 1;
        int within = tid + (i & 1) * 256;
        int row = within >> 2, c = (within & 3) * 16;
        const char* src = (tile == 0) ? srcA_h + row * strA + c
                        : (tile == 1) ? srcA_l + row * strA + c
                        : (tile == 2) ? srcB_h + row * strB + c
                                      : srcB_l + row * strB + c;
        cp16(dstb + tile * TILE_B + row * ROWB + c, src);
    }
}

// Full bf16 GEMM mainloop: 3-stage pipeline, one barrier per k-iter
__device__ __forceinline__ void gemm_mainloop(
    const bf16* __restrict__ Ah, const bf16* __restrict__ Al, int lda,
    const bf16* __restrict__ Bh, const bf16* __restrict__ Bl, int ldb,
    int kEnd, int rowBase, int colBase, unsigned smBase, float acc[2][8][4])
{
    const int tid = threadIdx.x;
    const int lane = tid & 31, wid = tid >> 5;
    const int wm = wid & 3, wn = wid >> 2;
    const int lrow = lane & 15, lk = (lane >> 4) * 16;
    const int kTiles = kEnd >> 5;

    load_tiles4(smBase, 0, Ah, Al, lda, Bh, Bl, ldb, rowBase, colBase, 0, tid);
    cp_commit();
    if (kTiles > 1) {
        load_tiles4(smBase, 1, Ah, Al, lda, Bh, Bl, ldb, rowBase, colBase, 32, tid);
        cp_commit();
    }

    int buf = 0;
    for (int it = 0; it < kTiles; ++it) {
        if (it + 1 < kTiles) cp_wait1(); else cp_wait0();
        __syncthreads();
        if (it + 2 < kTiles) {
            int nb = buf + 2; if (nb >= NSTAGE) nb -= NSTAGE;
            load_tiles4(smBase, nb, Ah, Al, lda, Bh, Bl, ldb,
                        rowBase, colBase, (it + 2) << 5, tid);
            cp_commit();
        }
        compute_tiles(smBase, buf, wm, wn, lrow, lk, acc);
        if (++buf == NSTAGE) buf = 0;
    }
}

// ---------------------------------------------------------------------------
// Stage 1: QKV projections. grid (8, 64, 3)
// ---------------------------------------------------------------------------
__global__ void __launch_bounds__(256) qkv_gemm(
    const float* __restrict__ bq, const float* __restrict__ bk,
    const float* __restrict__ bv)
{
    extern __shared__ char smc[];
    unsigned smBase = smem_u32(smc);
    const int tid = threadIdx.x, lane = tid & 31, wid = tid >> 5;
    const int wm = wid & 3, wn = wid >> 2;
    const int z = blockIdx.z;
    const int rowBase = blockIdx.y * 128, colBase = blockIdx.x * 128;

    const bf16* Bh = g_Wh + (size_t)z * EE * EE;
    const bf16* Bl = g_Wl + (size_t)z * EE * EE;
    const float* bias = (z == 0) ? bq : (z == 1) ? bk : bv;
    bf16* oh = (z == 0) ? g_qh : (z == 1) ? g_kh : g_vh;
    bf16* ol = (z == 0) ? g_ql : (z == 1) ? g_kl : g_vl;
    const float alpha = (z == 0) ? 0.03125f : 1.0f;

    float acc[2][8][4] = {};
    gemm_mainloop(g_xh, g_xl, EE, Bh, Bl, EE, EE, rowBase, colBase, smBase, acc);

    #pragma unroll
    for (int mi = 0; mi < 2; mi++)
        #pragma unroll
        for (int ni = 0; ni < 8; ni++) {
            int col = colBase + wn * 64 + ni * 8 + (lane & 3) * 2;
            float b0 = bias[col], b1 = bias[col + 1];
            #pragma unroll
            for (int h = 0; h < 2; h++) {
                int row = rowBase + wm * 32 + mi * 16 + (lane >> 2) + h * 8;
                float y0 = (acc[mi][ni][2 * h]     + b0) * alpha;
                float y1 = (acc[mi][ni][2 * h + 1] + b1) * alpha;
                bf16 h0 = __float2bfloat16(y0), h1 = __float2bfloat16(y1);
                bf16 l0 = __float2bfloat16(y0 - __bfloat162float(h0));
                bf16 l1 = __float2bfloat16(y1 - __bfloat162float(h1));
                size_t off = (size_t)row * EE + col;
                *(__nv_bfloat162*)(oh + off) = __halves2bfloat162(h0, h1);
                *(__nv_bfloat162*)(ol + off) = __halves2bfloat162(l0, l1);
            }
        }
}

// ---------------------------------------------------------------------------
// Stage 2: scores = q_scaled @ k^T (causal block skip). grid (16, 16, 4)
// ---------------------------------------------------------------------------
__global__ void __launch_bounds__(256) scores_gemm()
{
    if (blockIdx.x > blockIdx.y) return;
    extern __shared__ char smc[];
    unsigned smBase = smem_u32(smc);
    const int tid = threadIdx.x, lane = tid & 31, wid = tid >> 5;
    const int wm = wid & 3, wn = wid >> 2;
    const int z = blockIdx.z;
    const int rowBase = blockIdx.y * 128, colBase = blockIdx.x * 128;

    float acc[2][8][4] = {};
    gemm_mainloop(g_qh + (size_t)z * SS * EE, g_ql + (size_t)z * SS * EE, EE,
                  g_kh + (size_t)z * SS * EE, g_kl + (size_t)z * SS * EE, EE,
                  EE, rowBase, colBase, smBase, acc);

    float* out = g_sc + (size_t)z * SS * SS;
    #pragma unroll
    for (int mi = 0; mi < 2; mi++)
        #pragma unroll
        for (int ni = 0; ni < 8; ni++) {
            int col = colBase + wn * 64 + ni * 8 + (lane & 3) * 2;
            #pragma unroll
            for (int h = 0; h < 2; h++) {
                int row = rowBase + wm * 32 + mi * 16 + (lane >> 2) + h * 8;
                *(float2*)(out + (size_t)row * SS + col) =
                    make_float2(acc[mi][ni][2 * h], acc[mi][ni][2 * h + 1]);
            }
        }
}

// ---------------------------------------------------------------------------
// Stage 2b: per-row softmax stats (max, 1/sumexp). grid B*S
// ---------------------------------------------------------------------------
__global__ void stats_kernel()
{
    const int rowg = blockIdx.x;
    const int b = rowg >> 11;
    const int i = rowg & (SS - 1);
    const float* p = g_sc + (size_t)b * SS * SS + (size_t)i * SS;
    const int L = i + 1;

    __shared__ float red[8], red2[8];
    const int t = threadIdx.x, lane = t & 31, w = t >> 5;

    float m = -1e30f;
    for (int j = t; j < L; j += 256) m = fmaxf(m, p[j]);
    #pragma unroll
    for (int o = 16; o; o >>= 1) m = fmaxf(m, __shfl_xor_sync(~0u, m, o));
    if (lane == 0) red[w] = m;
    __syncthreads();
    m = red[0];
    #pragma unroll
    for (int ww = 1; ww < 8; ww++) m = fmaxf(m, red[ww]);

    float s = 0.0f;
    for (int j = t; j < L; j += 256) s += __expf(p[j] - m);
    #pragma unroll
    for (int o = 16; o; o >>= 1) s += __shfl_xor_sync(~0u, s, o);
    if (lane == 0) red2[w] = s;
    __syncthreads();
    s = red2[0];
    #pragma unroll
    for (int ww = 1; ww < 8; ww++) s += red2[ww];

    if (t == 0) {
        g_m[rowg] = m;
        g_inv[rowg] = 1.0f / s;
    }
}

// ---------------------------------------------------------------------------
// Stage 3: out = P @ vT with fused softmax. grid (8, 16, 4)
// 3-stage pipeline; A tile built in-register from fp32 scores each iter.
// ---------------------------------------------------------------------------
__global__ void __launch_bounds__(256) av_gemm(float* __restrict__ gout)
{
    extern __shared__ char smc[];
    unsigned smBase = smem_u32(smc);
    const int tid = threadIdx.x, lane = tid & 31, wid = tid >> 5;
    const int wm = wid & 3, wn = wid >> 2;
    const int lrow = lane & 15, lk = (lane >> 4) * 16;
    const int z = blockIdx.z;
    const int rowBase = blockIdx.y * 128, colBase = blockIdx.x * 128;
    const int kTiles = (blockIdx.y + 1) * 4;

    const bf16* Bh = g_vTh + (size_t)z * EE * SS;
    const bf16* Bl = g_vTl + (size_t)z * EE * SS;
    const float* sc = g_sc + (size_t)z * SS * SS;

    const int r = tid >> 1, ch = (tid & 1) * 16;
    const int grow = rowBase + r;
    const float rm = g_m[z * SS + grow];
    const float rinv = g_inv[z * SS + grow];
    const float* srow = sc + (size_t)grow * SS + ch;

    auto load_B = [&](int buf, int kt) {
        const unsigned dstb = smBase + buf * (4 * TILE_B);
        const char* sBh = (const char*)(Bh + (size_t)colBase * SS + kt);
        const char* sBl = (const char*)(Bl + (size_t)colBase * SS + kt);
        const size_t str = (size_t)SS * 2;
        #pragma unroll
        for (int i = 0; i < 4; i++) {
            const int tile = 2 + (i >> 1);
            int within = tid + (i & 1) * 256;
            int row = within >> 2, c = (within & 3) * 16;
            const char* src = (tile == 2) ? sBh + row * str + c : sBl + row * str + c;
            cp16(dstb + tile * TILE_B + row * ROWB + c, src);
        }
    };
    float4 sreg[4];
    auto ldg_A = [&](int kt) {
        const float* s0 = srow + kt;
        #pragma unroll
        for (int j = 0; j < 4; j++) sreg[j] = *(const float4*)(s0 + j * 4);
    };
    auto sts_A = [&](int buf, int kt) {
        char* base = smc + buf * (4 * TILE_B);
        #pragma unroll
        for (int j = 0; j < 4; j++) {
            float sv[4] = {sreg[j].x, sreg[j].y, sreg[j].z, sreg[j].w};
            float pv[4];
            #pragma unroll
            for (int e = 0; e < 4; e++) {
                int gcol = kt + ch + j * 4 + e;
                pv[e] = (gcol <= grow) ? __expf(sv[e] - rm) * rinv : 0.0f;
            }
            bf16 h0 = __float2bfloat16(pv[0]), h1 = __float2bfloat16(pv[1]);
            bf16 h2 = __float2bfloat16(pv[2]), h3 = __float2bfloat16(pv[3]);
            bf16 l0 = __float2bfloat16(pv[0] - __bfloat162float(h0));
            bf16 l1 = __float2bfloat16(pv[1] - __bfloat162float(h1));
            bf16 l2 = __float2bfloat16(pv[2] - __bfloat162float(h2));
            bf16 l3 = __float2bfloat16(pv[3] - __bfloat162float(h3));
            int boff = r * ROWB + (ch + j * 4) * 2;
            *(__nv_bfloat162*)(base + 0 * TILE_B + boff)     = __halves2bfloat162(h0, h1);
            *(__nv_bfloat162*)(base + 0 * TILE_B + boff + 4) = __halves2bfloat162(h2, h3);
            *(__nv_bfloat162*)(base + 1 * TILE_B + boff)     = __halves2bfloat162(l0, l1);
            *(__nv_bfloat162*)(base + 1 * TILE_B + boff + 4) = __halves2bfloat162(l2, l3);
        }
    };

    float acc[2][8][4] = {};

    // prologue
    load_B(0, 0);
    cp_commit();
    ldg_A(0);
    if (kTiles > 1) {
        load_B(1, 32);
        cp_commit();
    }

    int buf = 0;
    for (int it = 0; it < kTiles; ++it) {
        sts_A(buf, it << 5);               // regs for tile it -> smem A
        if (it + 1 < kTiles) cp_wait1(); else cp_wait0();
        __syncthreads();
        if (it + 2 < kTiles) {
            int nb = buf + 2; if (nb >= NSTAGE) nb -= NSTAGE;
            load_B(nb, (it + 2) << 5);
            cp_commit();
        }
        if (it + 1 < kTiles) ldg_A((it + 1) << 5);   // prefetch next scores
        compute_tiles(smBase, buf, wm, wn, lrow, lk, acc);
        if (++buf == NSTAGE) buf = 0;
    }

    float* out = gout + (size_t)z * SS * EE;
    #pragma unroll
    for (int mi = 0; mi < 2; mi++)
        #pragma unroll
        for (int ni = 0; ni < 8; ni++) {
            int col = colBase + wn * 64 + ni * 8 + (lane & 3) * 2;
            #pragma unroll
            for (int h = 0; h < 2; h++) {
                int row = rowBase + wm * 32 + mi * 16 + (lane >> 2) + h * 8;
                *(float2*)(out + (size_t)row * EE + col) =
                    make_float2(acc[mi][ni][2 * h], acc[mi][ni][2 * h + 1]);
            }
        }
}

// ---------------------------------------------------------------------------
// Elementwise: fp32 -> bf16 hi/lo split
// ---------------------------------------------------------------------------
__global__ void split_kernel(const float* __restrict__ src,
                             bf16* __restrict__ h, bf16* __restrict__ l)
{
    size_t i = ((size_t)blockIdx.x * 256 + threadIdx.x) * 4;
    float4 v = *(const float4*)(src + i);
    bf16 h0 = __float2bfloat16(v.x), h1 = __float2bfloat16(v.y);
    bf16 h2 = __float2bfloat16(v.z), h3 = __float2bfloat16(v.w);
    bf16 l0 = __float2bfloat16(v.x - __bfloat162float(h0));
    bf16 l1 = __float2bfloat16(v.y - __bfloat162float(h1));
    bf16 l2 = __float2bfloat16(v.z - __bfloat162float(h2));
    bf16 l3 = __float2bfloat16(v.w - __bfloat162float(h3));
    *(__nv_bfloat162*)(h + i)     = __halves2bfloat162(h0, h1);
    *(__nv_bfloat162*)(h + i + 2) = __halves2bfloat162(h2, h3);
    *(__nv_bfloat162*)(l + i)     = __halves2bfloat162(l0, l1);
    *(__nv_bfloat162*)(l + i + 2) = __halves2bfloat162(l2, l3);
}

// ---------------------------------------------------------------------------
// Transpose v (per batch): [S, E] -> [E, S], hi and lo
// ---------------------------------------------------------------------------
__global__ void transpose_v()
{
    __shared__ bf16 th[32][33], tl[32][33];
    const int z = blockIdx.z;
    const int s0 = blockIdx.x * 32, e0 = blockIdx.y * 32;
    const int tx = threadIdx.x, ty = threadIdx.y;
    #pragma unroll
    for (int j = 0; j < 32; j += 8) {
        size_t src = ((size_t)z * SS + s0 + ty + j) * EE + e0 + tx;
        th[ty + j][tx] = g_vh[src];
        tl[ty + j][tx] = g_vl[src];
    }
    __syncthreads();
    #pragma unroll
    for (int j = 0; j < 32; j += 8) {
        size_t dst = ((size_t)z * EE + e0 + ty + j) * SS + s0 + tx;
        g_vTh[dst] = th[tx][ty + j];
        g_vTl[dst] = tl[tx][ty + j];
    }
}

// ---------------------------------------------------------------------------
// Launch
// ---------------------------------------------------------------------------
extern "C" void kernel_launch(void* const* d_in, const int* in_sizes, int n_in,
                              void* d_out, int out_size)
{
    const float* x  = (const float*)d_in[0];
    const float* Wq = (const float*)d_in[2];
    const float* bq = (const float*)d_in[3];
    const float* Wk = (const float*)d_in[4];
    const float* bk = (const float*)d_in[5];
    const float* Wv = (const float*)d_in[6];
    const float* bv = (const float*)d_in[7];
    float* out = (float*)d_out;

    bf16 *xh, *xl, *wh, *wl;
    cudaGetSymbolAddress((void**)&xh, g_xh);
    cudaGetSymbolAddress((void**)&xl, g_xl);
    cudaGetSymbolAddress((void**)&wh, g_Wh);
    cudaGetSymbolAddress((void**)&wl, g_Wl);

    static bool attr_done = false;
    if (!attr_done) {
        cudaFuncSetAttribute(qkv_gemm,    cudaFuncAttributeMaxDynamicSharedMemorySize, SMEM_BYTES);
        cudaFuncSetAttribute(scores_gemm, cudaFuncAttributeMaxDynamicSharedMemorySize, SMEM_BYTES);
        cudaFuncSetAttribute(av_gemm,     cudaFuncAttributeMaxDynamicSharedMemorySize, SMEM_BYTES);
        attr_done = true;
    }

    // 1) hi/lo splits
    split_kernel<<<(BB * SS * EE) / 1024, 256>>>(x, xh, xl);
    split_kernel<<<(EE * EE) / 1024, 256>>>(Wq, wh,                       wl);
    split_kernel<<<(EE * EE) / 1024, 256>>>(Wk, wh + (size_t)EE * EE,     wl + (size_t)EE * EE);
    split_kernel<<<(EE * EE) / 1024, 256>>>(Wv, wh + 2 * (size_t)EE * EE, wl + 2 * (size_t)EE * EE);

    // 2) QKV projections (q pre-scaled by 1/32)
    qkv_gemm<<<dim3(EE / 128, (BB * SS) / 128, 3), 256, SMEM_BYTES>>>(bq, bk, bv);

    // 3) transpose v
    transpose_v<<<dim3(SS / 32, EE / 32, BB), dim3(32, 8)>>>();

    // 4) scores (lower-triangular blocks)
    scores_gemm<<<dim3(SS / 128, SS / 128, BB), 256, SMEM_BYTES>>>();

    // 5) per-row softmax stats
    stats_kernel<<<BB * SS, 256>>>();

    // 6) fused softmax + P @ vT
    av_gemm<<<dim3(EE / 128, SS / 128, BB), 256, SMEM_BYTES>>>(out);
}

// round 6
// speedup vs baseline: 1.1995x; 1.1995x over previous
#include <cuda_runtime.h>
#include <cuda_bf16.h>

#define BB 4
#define SS 2048
#define EE 1024

typedef __nv_bfloat16 bf16;

// ---------------------------------------------------------------------------
// Scratch (device globals — no allocation allowed)
// ---------------------------------------------------------------------------
__device__ float g_sc[(size_t)BB * SS * SS];
__device__ float g_m[BB * SS], g_inv[BB * SS];
__device__ bf16 g_xh[(size_t)BB * SS * EE], g_xl[(size_t)BB * SS * EE];
__device__ bf16 g_Wh[3 * (size_t)EE * EE], g_Wl[3 * (size_t)EE * EE];
__device__ bf16 g_qh[(size_t)BB * SS * EE], g_ql[(size_t)BB * SS * EE];
__device__ bf16 g_kh[(size_t)BB * SS * EE], g_kl[(size_t)BB * SS * EE];
__device__ bf16 g_vh[(size_t)BB * SS * EE], g_vl[(size_t)BB * SS * EE];
__device__ bf16 g_vTh[(size_t)BB * EE * SS], g_vTl[(size_t)BB * EE * SS];

// ---------------------------------------------------------------------------
// PTX helpers (baseline sm_80+ features only — plain sm_103 target)
// ---------------------------------------------------------------------------
__device__ __forceinline__ unsigned smem_u32(const void* p) {
    unsigned a;
    asm("{ .reg .u64 t; cvta.to.shared.u64 t, %1; cvt.u32.u64 %0, t; }"
        : "=r"(a) : "l"(p));
    return a;
}
__device__ __forceinline__ void cp16(unsigned dst, const void* src) {
    asm volatile("cp.async.cg.shared.global [%0], [%1], 16;"
                 :: "r"(dst), "l"(src) : "memory");
}
__device__ __forceinline__ void cp_commit() {
    asm volatile("cp.async.commit_group;" ::: "memory");
}
__device__ __forceinline__ void cp_wait1() {
    asm volatile("cp.async.wait_group 1;" ::: "memory");
}
__device__ __forceinline__ void cp_wait0() {
    asm volatile("cp.async.wait_group 0;" ::: "memory");
}
__device__ __forceinline__ void ldsm4(unsigned& r0, unsigned& r1, unsigned& r2,
                                      unsigned& r3, unsigned addr) {
    asm volatile("ldmatrix.sync.aligned.m8n8.x4.shared.b16 {%0,%1,%2,%3}, [%4];"
                 : "=r"(r0), "=r"(r1), "=r"(r2), "=r"(r3) : "r"(addr));
}
__device__ __forceinline__ void mma16816(float* d, const unsigned* a,
                                         unsigned b0, unsigned b1) {
    asm volatile(
        "mma.sync.aligned.m16n8k16.row.col.f32.bf16.bf16.f32 "
        "{%0,%1,%2,%3}, {%4,%5,%6,%7}, {%8,%9}, {%0,%1,%2,%3};"
        : "+f"(d[0]), "+f"(d[1]), "+f"(d[2]), "+f"(d[3])
        : "r"(a[0]), "r"(a[1]), "r"(a[2]), "r"(a[3]), "r"(b0), "r"(b1));
}

// ---------------------------------------------------------------------------
// Tile layout: 128 rows x 32 bf16 = 64B rows (no padding). 16B-unit swizzle:
// phys unit = c ^ ((row>>1)&3)  -> conflict-free ldmatrix, zero smem waste.
// Per stage: 4 tiles [Ah, Al, Bh, Bl]. 3 stages = 96KB -> 2 CTAs/SM.
// ---------------------------------------------------------------------------
#define TILE_B 8192
#define NSTAGE 3
#define SMEM_BYTES (NSTAGE * 4 * TILE_B)    // 98304
#define SWOFF(row, c) ((row) * 64 + (((c) ^ (((row) >> 1) & 3)) << 4))

// 3-pass compute on one buffered k-tile: acc += Ah*Bh + Al*Bh + Ah*Bl
__device__ __forceinline__ void compute_tiles(unsigned smBase, int buf,
                                              int wm, int wn, int lane,
                                              float acc[2][8][4])
{
    const unsigned tb = smBase + buf * (4 * TILE_B);
    const int lrow = lane & 15;
    const int lcu = lane >> 4;          // 16B-unit within k-half
    #pragma unroll
    for (int ks = 0; ks < 2; ks++) {
        const int cu = ks * 2 + lcu;
        unsigned ah[2][4], al[2][4], bh[4][4], bl[4][4];
        #pragma unroll
        for (int mi = 0; mi < 2; mi++) {
            int row = wm * 32 + mi * 16 + lrow;
            unsigned off = SWOFF(row, cu);
            ldsm4(ah[mi][0], ah[mi][1], ah[mi][2], ah[mi][3], tb + 0 * TILE_B + off);
            ldsm4(al[mi][0], al[mi][1], al[mi][2], al[mi][3], tb + 1 * TILE_B + off);
        }
        #pragma unroll
        for (int nj = 0; nj < 4; nj++) {
            int row = wn * 64 + nj * 16 + lrow;
            unsigned off = SWOFF(row, cu);
            ldsm4(bh[nj][0], bh[nj][1], bh[nj][2], bh[nj][3], tb + 2 * TILE_B + off);
            ldsm4(bl[nj][0], bl[nj][1], bl[nj][2], bl[nj][3], tb + 3 * TILE_B + off);
        }
        #pragma unroll
        for (int mi = 0; mi < 2; mi++)
            #pragma unroll
            for (int nj = 0; nj < 4; nj++) {
                mma16816(acc[mi][2 * nj],     ah[mi], bh[nj][0], bh[nj][2]);
                mma16816(acc[mi][2 * nj + 1], ah[mi], bh[nj][1], bh[nj][3]);
                mma16816(acc[mi][2 * nj],     al[mi], bh[nj][0], bh[nj][2]);
                mma16816(acc[mi][2 * nj + 1], al[mi], bh[nj][1], bh[nj][3]);
                mma16816(acc[mi][2 * nj],     ah[mi], bl[nj][0], bl[nj][2]);
                mma16816(acc[mi][2 * nj + 1], ah[mi], bl[nj][1], bl[nj][3]);
            }
    }
}

// cp.async loader for all 4 bf16 tiles (swizzled dst)
__device__ __forceinline__ void load_tiles4(unsigned smBase, int buf,
    const bf16* Ah, const bf16* Al, int lda,
    const bf16* Bh, const bf16* Bl, int ldb,
    int rowBase, int colBase, int kt, int tid)
{
    const unsigned dstb = smBase + buf * (4 * TILE_B);
    const char* srcA_h = (const char*)(Ah + (size_t)rowBase * lda + kt);
    const char* srcA_l = (const char*)(Al + (size_t)rowBase * lda + kt);
    const char* srcB_h = (const char*)(Bh + (size_t)colBase * ldb + kt);
    const char* srcB_l = (const char*)(Bl + (size_t)colBase * ldb + kt);
    const size_t strA = (size_t)lda * 2, strB = (size_t)ldb * 2;
    #pragma unroll
    for (int i = 0; i < 8; i++) {
        const int tile = i >> 1;
        int within = tid + (i & 1) * 256;
        int row = within >> 2, c = within & 3;
        const char* src = (tile == 0) ? srcA_h + row * strA + c * 16
                        : (tile == 1) ? srcA_l + row * strA + c * 16
                        : (tile == 2) ? srcB_h + row * strB + c * 16
                                      : srcB_l + row * strB + c * 16;
        cp16(dstb + tile * TILE_B + SWOFF(row, c), src);
    }
}

// Full bf16 GEMM mainloop: 3-stage pipeline, ONE barrier per k-iter
__device__ __forceinline__ void gemm_mainloop(
    const bf16* __restrict__ Ah, const bf16* __restrict__ Al, int lda,
    const bf16* __restrict__ Bh, const bf16* __restrict__ Bl, int ldb,
    int kEnd, int rowBase, int colBase, unsigned smBase, float acc[2][8][4])
{
    const int tid = threadIdx.x;
    const int lane = tid & 31, wid = tid >> 5;
    const int wm = wid & 3, wn = wid >> 2;
    const int kTiles = kEnd >> 5;

    load_tiles4(smBase, 0, Ah, Al, lda, Bh, Bl, ldb, rowBase, colBase, 0, tid);
    cp_commit();
    if (kTiles > 1) {
        load_tiles4(smBase, 1, Ah, Al, lda, Bh, Bl, ldb, rowBase, colBase, 32, tid);
        cp_commit();
    }

    int buf = 0;
    for (int it = 0; it < kTiles; ++it) {
        if (it + 1 < kTiles) cp_wait1(); else cp_wait0();
        __syncthreads();
        if (it + 2 < kTiles) {
            int nb = buf + 2; if (nb >= NSTAGE) nb -= NSTAGE;
            load_tiles4(smBase, nb, Ah, Al, lda, Bh, Bl, ldb,
                        rowBase, colBase, (it + 2) << 5, tid);
            cp_commit();
        }
        compute_tiles(smBase, buf, wm, wn, lane, acc);
        if (++buf == NSTAGE) buf = 0;
    }
}

// ---------------------------------------------------------------------------
// Stage 1: QKV projections. grid (8, 64, 3)
// ---------------------------------------------------------------------------
__global__ void __launch_bounds__(256, 2) qkv_gemm(
    const float* __restrict__ bq, const float* __restrict__ bk,
    const float* __restrict__ bv)
{
    extern __shared__ char smc[];
    unsigned smBase = smem_u32(smc);
    const int tid = threadIdx.x, lane = tid & 31, wid = tid >> 5;
    const int wm = wid & 3, wn = wid >> 2;
    const int z = blockIdx.z;
    const int rowBase = blockIdx.y * 128, colBase = blockIdx.x * 128;

    const bf16* Bh = g_Wh + (size_t)z * EE * EE;
    const bf16* Bl = g_Wl + (size_t)z * EE * EE;
    const float* bias = (z == 0) ? bq : (z == 1) ? bk : bv;
    bf16* oh = (z == 0) ? g_qh : (z == 1) ? g_kh : g_vh;
    bf16* ol = (z == 0) ? g_ql : (z == 1) ? g_kl : g_vl;
    const float alpha = (z == 0) ? 0.03125f : 1.0f;

    float acc[2][8][4] = {};
    gemm_mainloop(g_xh, g_xl, EE, Bh, Bl, EE, EE, rowBase, colBase, smBase, acc);

    #pragma unroll
    for (int mi = 0; mi < 2; mi++)
        #pragma unroll
        for (int ni = 0; ni < 8; ni++) {
            int col = colBase + wn * 64 + ni * 8 + (lane & 3) * 2;
            float b0 = bias[col], b1 = bias[col + 1];
            #pragma unroll
            for (int h = 0; h < 2; h++) {
                int row = rowBase + wm * 32 + mi * 16 + (lane >> 2) + h * 8;
                float y0 = (acc[mi][ni][2 * h]     + b0) * alpha;
                float y1 = (acc[mi][ni][2 * h + 1] + b1) * alpha;
                bf16 h0 = __float2bfloat16(y0), h1 = __float2bfloat16(y1);
                bf16 l0 = __float2bfloat16(y0 - __bfloat162float(h0));
                bf16 l1 = __float2bfloat16(y1 - __bfloat162float(h1));
                size_t off = (size_t)row * EE + col;
                *(__nv_bfloat162*)(oh + off) = __halves2bfloat162(h0, h1);
                *(__nv_bfloat162*)(ol + off) = __halves2bfloat162(l0, l1);
            }
        }
}

// ---------------------------------------------------------------------------
// Stage 2: scores = q_scaled @ k^T (causal block skip). grid (16, 16, 4)
// ---------------------------------------------------------------------------
__global__ void __launch_bounds__(256, 2) scores_gemm()
{
    if (blockIdx.x > blockIdx.y) return;
    extern __shared__ char smc[];
    unsigned smBase = smem_u32(smc);
    const int tid = threadIdx.x, lane = tid & 31, wid = tid >> 5;
    const int wm = wid & 3, wn = wid >> 2;
    const int z = blockIdx.z;
    const int rowBase = blockIdx.y * 128, colBase = blockIdx.x * 128;

    float acc[2][8][4] = {};
    gemm_mainloop(g_qh + (size_t)z * SS * EE, g_ql + (size_t)z * SS * EE, EE,
                  g_kh + (size_t)z * SS * EE, g_kl + (size_t)z * SS * EE, EE,
                  EE, rowBase, colBase, smBase, acc);

    float* out = g_sc + (size_t)z * SS * SS;
    #pragma unroll
    for (int mi = 0; mi < 2; mi++)
        #pragma unroll
        for (int ni = 0; ni < 8; ni++) {
            int col = colBase + wn * 64 + ni * 8 + (lane & 3) * 2;
            #pragma unroll
            for (int h = 0; h < 2; h++) {
                int row = rowBase + wm * 32 + mi * 16 + (lane >> 2) + h * 8;
                *(float2*)(out + (size_t)row * SS + col) =
                    make_float2(acc[mi][ni][2 * h], acc[mi][ni][2 * h + 1]);
            }
        }
}

// ---------------------------------------------------------------------------
// Stage 2b: per-row softmax stats (max, 1/sumexp). grid B*S
// ---------------------------------------------------------------------------
__global__ void stats_kernel()
{
    const int rowg = blockIdx.x;
    const int b = rowg >> 11;
    const int i = rowg & (SS - 1);
    const float* p = g_sc + (size_t)b * SS * SS + (size_t)i * SS;
    const int L = i + 1;

    __shared__ float red[8], red2[8];
    const int t = threadIdx.x, lane = t & 31, w = t >> 5;

    float m = -1e30f;
    for (int j = t; j < L; j += 256) m = fmaxf(m, p[j]);
    #pragma unroll
    for (int o = 16; o; o >>= 1) m = fmaxf(m, __shfl_xor_sync(~0u, m, o));
    if (lane == 0) red[w] = m;
    __syncthreads();
    m = red[0];
    #pragma unroll
    for (int ww = 1; ww < 8; ww++) m = fmaxf(m, red[ww]);

    float s = 0.0f;
    for (int j = t; j < L; j += 256) s += __expf(p[j] - m);
    #pragma unroll
    for (int o = 16; o; o >>= 1) s += __shfl_xor_sync(~0u, s, o);
    if (lane == 0) red2[w] = s;
    __syncthreads();
    s = red2[0];
    #pragma unroll
    for (int ww = 1; ww < 8; ww++) s += red2[ww];

    if (t == 0) {
        g_m[rowg] = m;
        g_inv[rowg] = 1.0f / s;
    }
}

// ---------------------------------------------------------------------------
// Stage 3: out = P @ vT with fused softmax. grid (8, 16, 4)
// ---------------------------------------------------------------------------
__global__ void __launch_bounds__(256, 2) av_gemm(float* __restrict__ gout)
{
    extern __shared__ char smc[];
    unsigned smBase = smem_u32(smc);
    const int tid = threadIdx.x, lane = tid & 31, wid = tid >> 5;
    const int wm = wid & 3, wn = wid >> 2;
    const int z = blockIdx.z;
    const int rowBase = blockIdx.y * 128, colBase = blockIdx.x * 128;
    const int kTiles = (blockIdx.y + 1) * 4;

    const bf16* Bh = g_vTh + (size_t)z * EE * SS;
    const bf16* Bl = g_vTl + (size_t)z * EE * SS;
    const float* sc = g_sc + (size_t)z * SS * SS;

    const int r = tid >> 1, ch = (tid & 1) * 16;
    const int grow = rowBase + r;
    const float rm = g_m[z * SS + grow];
    const float rinv = g_inv[z * SS + grow];
    const float* srow = sc + (size_t)grow * SS + ch;

    auto load_B = [&](int buf, int kt) {
        const unsigned dstb = smBase + buf * (4 * TILE_B);
        const char* sBh = (const char*)(Bh + (size_t)colBase * SS + kt);
        const char* sBl = (const char*)(Bl + (size_t)colBase * SS + kt);
        const size_t str = (size_t)SS * 2;
        #pragma unroll
        for (int i = 0; i < 4; i++) {
            const int tile = 2 + (i >> 1);
            int within = tid + (i & 1) * 256;
            int row = within >> 2, c = within & 3;
            const char* src = (tile == 2) ? sBh + row * str + c * 16
                                          : sBl + row * str + c * 16;
            cp16(dstb + tile * TILE_B + SWOFF(row, c), src);
        }
    };
    float4 sreg[4];
    auto ldg_A = [&](int kt) {
        const float* s0 = srow + kt;
        #pragma unroll
        for (int j = 0; j < 4; j++) sreg[j] = *(const float4*)(s0 + j * 4);
    };
    auto sts_A = [&](int buf, int kt) {
        char* base = smc + buf * (4 * TILE_B);
        const int sw = ((r >> 1) & 3);
        #pragma unroll
        for (int j = 0; j < 4; j++) {
            float sv[4] = {sreg[j].x, sreg[j].y, sreg[j].z, sreg[j].w};
            float pv[4];
            #pragma unroll
            for (int e = 0; e < 4; e++) {
                int gcol = kt + ch + j * 4 + e;
                pv[e] = (gcol <= grow) ? __expf(sv[e] - rm) * rinv : 0.0f;
            }
            bf16 h0 = __float2bfloat16(pv[0]), h1 = __float2bfloat16(pv[1]);
            bf16 h2 = __float2bfloat16(pv[2]), h3 = __float2bfloat16(pv[3]);
            bf16 l0 = __float2bfloat16(pv[0] - __bfloat162float(h0));
            bf16 l1 = __float2bfloat16(pv[1] - __bfloat162float(h1));
            bf16 l2 = __float2bfloat16(pv[2] - __bfloat162float(h2));
            bf16 l3 = __float2bfloat16(pv[3] - __bfloat162float(h3));
            int ccb = ch + j * 4;
            int unit = ccb >> 3;
            int boff = r * 64 + ((unit ^ sw) << 4) + (ccb & 7) * 2;
            *(__nv_bfloat162*)(base + 0 * TILE_B + boff)     = __halves2bfloat162(h0, h1);
            *(__nv_bfloat162*)(base + 0 * TILE_B + boff + 4) = __halves2bfloat162(h2, h3);
            *(__nv_bfloat162*)(base + 1 * TILE_B + boff)     = __halves2bfloat162(l0, l1);
            *(__nv_bfloat162*)(base + 1 * TILE_B + boff + 4) = __halves2bfloat162(l2, l3);
        }
    };

    float acc[2][8][4] = {};

    load_B(0, 0);
    cp_commit();
    ldg_A(0);
    if (kTiles > 1) {
        load_B(1, 32);
        cp_commit();
    }

    int buf = 0;
    for (int it = 0; it < kTiles; ++it) {
        sts_A(buf, it << 5);
        if (it + 1 < kTiles) cp_wait1(); else cp_wait0();
        __syncthreads();
        if (it + 2 < kTiles) {
            int nb = buf + 2; if (nb >= NSTAGE) nb -= NSTAGE;
            load_B(nb, (it + 2) << 5);
            cp_commit();
        }
        if (it + 1 < kTiles) ldg_A((it + 1) << 5);
        compute_tiles(smBase, buf, wm, wn, lane, acc);
        if (++buf == NSTAGE) buf = 0;
    }

    float* out = gout + (size_t)z * SS * EE;
    #pragma unroll
    for (int mi = 0; mi < 2; mi++)
        #pragma unroll
        for (int ni = 0; ni < 8; ni++) {
            int col = colBase + wn * 64 + ni * 8 + (lane & 3) * 2;
            #pragma unroll
            for (int h = 0; h < 2; h++) {
                int row = rowBase + wm * 32 + mi * 16 + (lane >> 2) + h * 8;
                *(float2*)(out + (size_t)row * EE + col) =
                    make_float2(acc[mi][ni][2 * h], acc[mi][ni][2 * h + 1]);
            }
        }
}

// ---------------------------------------------------------------------------
// Elementwise: fp32 -> bf16 hi/lo split
// ---------------------------------------------------------------------------
__global__ void split_kernel(const float* __restrict__ src,
                             bf16* __restrict__ h, bf16* __restrict__ l)
{
    size_t i = ((size_t)blockIdx.x * 256 + threadIdx.x) * 4;
    float4 v = *(const float4*)(src + i);
    bf16 h0 = __float2bfloat16(v.x), h1 = __float2bfloat16(v.y);
    bf16 h2 = __float2bfloat16(v.z), h3 = __float2bfloat16(v.w);
    bf16 l0 = __float2bfloat16(v.x - __bfloat162float(h0));
    bf16 l1 = __float2bfloat16(v.y - __bfloat162float(h1));
    bf16 l2 = __float2bfloat16(v.z - __bfloat162float(h2));
    bf16 l3 = __float2bfloat16(v.w - __bfloat162float(h3));
    *(__nv_bfloat162*)(h + i)     = __halves2bfloat162(h0, h1);
    *(__nv_bfloat162*)(h + i + 2) = __halves2bfloat162(h2, h3);
    *(__nv_bfloat162*)(l + i)     = __halves2bfloat162(l0, l1);
    *(__nv_bfloat162*)(l + i + 2) = __halves2bfloat162(l2, l3);
}

// ---------------------------------------------------------------------------
// Transpose v (per batch): [S, E] -> [E, S], hi and lo
// ---------------------------------------------------------------------------
__global__ void transpose_v()
{
    __shared__ bf16 th[32][33], tl[32][33];
    const int z = blockIdx.z;
    const int s0 = blockIdx.x * 32, e0 = blockIdx.y * 32;
    const int tx = threadIdx.x, ty = threadIdx.y;
    #pragma unroll
    for (int j = 0; j < 32; j += 8) {
        size_t src = ((size_t)z * SS + s0 + ty + j) * EE + e0 + tx;
        th[ty + j][tx] = g_vh[src];
        tl[ty + j][tx] = g_vl[src];
    }
    __syncthreads();
    #pragma unroll
    for (int j = 0; j < 32; j += 8) {
        size_t dst = ((size_t)z * EE + e0 + ty + j) * SS + s0 + tx;
        g_vTh[dst] = th[tx][ty + j];
        g_vTl[dst] = tl[tx][ty + j];
    }
}

// ---------------------------------------------------------------------------
// Launch
// ---------------------------------------------------------------------------
extern "C" void kernel_launch(void* const* d_in, const int* in_sizes, int n_in,
                              void* d_out, int out_size)
{
    const float* x  = (const float*)d_in[0];
    const float* Wq = (const float*)d_in[2];
    const float* bq = (const float*)d_in[3];
    const float* Wk = (const float*)d_in[4];
    const float* bk = (const float*)d_in[5];
    const float* Wv = (const float*)d_in[6];
    const float* bv = (const float*)d_in[7];
    float* out = (float*)d_out;

    bf16 *xh, *xl, *wh, *wl;
    cudaGetSymbolAddress((void**)&xh, g_xh);
    cudaGetSymbolAddress((void**)&xl, g_xl);
    cudaGetSymbolAddress((void**)&wh, g_Wh);
    cudaGetSymbolAddress((void**)&wl, g_Wl);

    static bool attr_done = false;
    if (!attr_done) {
        cudaFuncSetAttribute(qkv_gemm,    cudaFuncAttributeMaxDynamicSharedMemorySize, SMEM_BYTES);
        cudaFuncSetAttribute(scores_gemm, cudaFuncAttributeMaxDynamicSharedMemorySize, SMEM_BYTES);
        cudaFuncSetAttribute(av_gemm,     cudaFuncAttributeMaxDynamicSharedMemorySize, SMEM_BYTES);
        attr_done = true;
    }

    // 1) hi/lo splits
    split_kernel<<<(BB * SS * EE) / 1024, 256>>>(x, xh, xl);
    split_kernel<<<(EE * EE) / 1024, 256>>>(Wq, wh,                       wl);
    split_kernel<<<(EE * EE) / 1024, 256>>>(Wk, wh + (size_t)EE * EE,     wl + (size_t)EE * EE);
    split_kernel<<<(EE * EE) / 1024, 256>>>(Wv, wh + 2 * (size_t)EE * EE, wl + 2 * (size_t)EE * EE);

    // 2) QKV projections (q pre-scaled by 1/32)
    qkv_gemm<<<dim3(EE / 128, (BB * SS) / 128, 3), 256, SMEM_BYTES>>>(bq, bk, bv);

    // 3) transpose v
    transpose_v<<<dim3(SS / 32, EE / 32, BB), dim3(32, 8)>>>();

    // 4) scores (lower-triangular blocks)
    scores_gemm<<<dim3(SS / 128, SS / 128, BB), 256, SMEM_BYTES>>>();

    // 5) per-row softmax stats
    stats_kernel<<<BB * SS, 256>>>();

    // 6) fused softmax + P @ vT
    av_gemm<<<dim3(EE / 128, SS / 128, BB), 256, SMEM_BYTES>>>(out);
}

// round 7
// speedup vs baseline: 1.2104x; 1.0091x over previous
#include <cuda_runtime.h>
#include <cuda_bf16.h>

#define BB 4
#define SS 2048
#define EE 1024

typedef __nv_bfloat16 bf16;

// ---------------------------------------------------------------------------
// Scratch (device globals — no allocation allowed)
// ---------------------------------------------------------------------------
__device__ float g_sc[(size_t)BB * SS * SS];
__device__ float g_m[BB * SS], g_inv[BB * SS];
__device__ bf16 g_xh[(size_t)BB * SS * EE], g_xl[(size_t)BB * SS * EE];
__device__ bf16 g_Wh[3 * (size_t)EE * EE], g_Wl[3 * (size_t)EE * EE];
__device__ bf16 g_qh[(size_t)BB * SS * EE], g_ql[(size_t)BB * SS * EE];
__device__ bf16 g_kh[(size_t)BB * SS * EE], g_kl[(size_t)BB * SS * EE];
__device__ bf16 g_vh[(size_t)BB * SS * EE], g_vl[(size_t)BB * SS * EE];
__device__ bf16 g_vTh[(size_t)BB * EE * SS], g_vTl[(size_t)BB * EE * SS];

// ---------------------------------------------------------------------------
// PTX helpers (baseline sm_80+ features only — plain sm_103 target)
// ---------------------------------------------------------------------------
__device__ __forceinline__ unsigned smem_u32(const void* p) {
    unsigned a;
    asm("{ .reg .u64 t; cvta.to.shared.u64 t, %1; cvt.u32.u64 %0, t; }"
        : "=r"(a) : "l"(p));
    return a;
}
__device__ __forceinline__ void cp16(unsigned dst, const void* src) {
    asm volatile("cp.async.cg.shared.global [%0], [%1], 16;"
                 :: "r"(dst), "l"(src) : "memory");
}
__device__ __forceinline__ void cp_commit() {
    asm volatile("cp.async.commit_group;" ::: "memory");
}
__device__ __forceinline__ void cp_wait1() {
    asm volatile("cp.async.wait_group 1;" ::: "memory");
}
__device__ __forceinline__ void cp_wait0() {
    asm volatile("cp.async.wait_group 0;" ::: "memory");
}
__device__ __forceinline__ void ldsm4(unsigned& r0, unsigned& r1, unsigned& r2,
                                      unsigned& r3, unsigned addr) {
    asm volatile("ldmatrix.sync.aligned.m8n8.x4.shared.b16 {%0,%1,%2,%3}, [%4];"
                 : "=r"(r0), "=r"(r1), "=r"(r2), "=r"(r3) : "r"(addr));
}
__device__ __forceinline__ void mma16816(float* d, const unsigned* a,
                                         unsigned b0, unsigned b1) {
    asm volatile(
        "mma.sync.aligned.m16n8k16.row.col.f32.bf16.bf16.f32 "
        "{%0,%1,%2,%3}, {%4,%5,%6,%7}, {%8,%9}, {%0,%1,%2,%3};"
        : "+f"(d[0]), "+f"(d[1]), "+f"(d[2]), "+f"(d[3])
        : "r"(a[0]), "r"(a[1]), "r"(a[2]), "r"(a[3]), "r"(b0), "r"(b1));
}

// ---------------------------------------------------------------------------
// Tile layout: 128 rows x 32 bf16 = 64B rows, XOR-swizzled 16B units.
// Per stage: 4 tiles [Ah, Al, Bh, Bl]. 3 stages = 96KB -> 2 CTAs/SM.
// ---------------------------------------------------------------------------
#define TILE_B 8192
#define NSTAGE 3
#define SMEM_BYTES (NSTAGE * 4 * TILE_B)    // 98304
#define SWOFF(row, c) ((row) * 64 + (((c) ^ (((row) >> 1) & 3)) << 4))

// 3-pass compute on one buffered k-tile: acc += Ah*Bh + Al*Bh + Ah*Bl
__device__ __forceinline__ void compute_tiles(unsigned smBase, int buf,
                                              int wm, int wn, int lane,
                                              float acc[2][8][4])
{
    const unsigned tb = smBase + buf * (4 * TILE_B);
    const int lrow = lane & 15;
    const int lcu = lane >> 4;
    #pragma unroll
    for (int ks = 0; ks < 2; ks++) {
        const int cu = ks * 2 + lcu;
        unsigned ah[2][4], al[2][4], bh[4][4], bl[4][4];
        #pragma unroll
        for (int mi = 0; mi < 2; mi++) {
            int row = wm * 32 + mi * 16 + lrow;
            unsigned off = SWOFF(row, cu);
            ldsm4(ah[mi][0], ah[mi][1], ah[mi][2], ah[mi][3], tb + 0 * TILE_B + off);
            ldsm4(al[mi][0], al[mi][1], al[mi][2], al[mi][3], tb + 1 * TILE_B + off);
        }
        #pragma unroll
        for (int nj = 0; nj < 4; nj++) {
            int row = wn * 64 + nj * 16 + lrow;
            unsigned off = SWOFF(row, cu);
            ldsm4(bh[nj][0], bh[nj][1], bh[nj][2], bh[nj][3], tb + 2 * TILE_B + off);
            ldsm4(bl[nj][0], bl[nj][1], bl[nj][2], bl[nj][3], tb + 3 * TILE_B + off);
        }
        #pragma unroll
        for (int mi = 0; mi < 2; mi++)
            #pragma unroll
            for (int nj = 0; nj < 4; nj++) {
                mma16816(acc[mi][2 * nj],     ah[mi], bh[nj][0], bh[nj][2]);
                mma16816(acc[mi][2 * nj + 1], ah[mi], bh[nj][1], bh[nj][3]);
                mma16816(acc[mi][2 * nj],     al[mi], bh[nj][0], bh[nj][2]);
                mma16816(acc[mi][2 * nj + 1], al[mi], bh[nj][1], bh[nj][3]);
                mma16816(acc[mi][2 * nj],     ah[mi], bl[nj][0], bl[nj][2]);
                mma16816(acc[mi][2 * nj + 1], ah[mi], bl[nj][1], bl[nj][3]);
            }
    }
}

// cp.async loader for all 4 bf16 tiles (swizzled dst)
__device__ __forceinline__ void load_tiles4(unsigned smBase, int buf,
    const bf16* Ah, const bf16* Al, int lda,
    const bf16* Bh, const bf16* Bl, int ldb,
    int rowBase, int colBase, int kt, int tid)
{
    const unsigned dstb = smBase + buf * (4 * TILE_B);
    const char* srcA_h = (const char*)(Ah + (size_t)rowBase * lda + kt);
    const char* srcA_l = (const char*)(Al + (size_t)rowBase * lda + kt);
    const char* srcB_h = (const char*)(Bh + (size_t)colBase * ldb + kt);
    const char* srcB_l = (const char*)(Bl + (size_t)colBase * ldb + kt);
    const size_t strA = (size_t)lda * 2, strB = (size_t)ldb * 2;
    #pragma unroll
    for (int i = 0; i < 8; i++) {
        const int tile = i >> 1;
        int within = tid + (i & 1) * 256;
        int row = within >> 2, c = within & 3;
        const char* src = (tile == 0) ? srcA_h + row * strA + c * 16
                        : (tile == 1) ? srcA_l + row * strA + c * 16
                        : (tile == 2) ? srcB_h + row * strB + c * 16
                                      : srcB_l + row * strB + c * 16;
        cp16(dstb + tile * TILE_B + SWOFF(row, c), src);
    }
}

// Full bf16 GEMM mainloop: 3-stage pipeline, ONE barrier per k-iter
__device__ __forceinline__ void gemm_mainloop(
    const bf16* __restrict__ Ah, const bf16* __restrict__ Al, int lda,
    const bf16* __restrict__ Bh, const bf16* __restrict__ Bl, int ldb,
    int kEnd, int rowBase, int colBase, unsigned smBase, float acc[2][8][4])
{
    const int tid = threadIdx.x;
    const int lane = tid & 31, wid = tid >> 5;
    const int wm = wid & 3, wn = wid >> 2;
    const int kTiles = kEnd >> 5;

    load_tiles4(smBase, 0, Ah, Al, lda, Bh, Bl, ldb, rowBase, colBase, 0, tid);
    cp_commit();
    if (kTiles > 1) {
        load_tiles4(smBase, 1, Ah, Al, lda, Bh, Bl, ldb, rowBase, colBase, 32, tid);
        cp_commit();
    }

    int buf = 0;
    for (int it = 0; it < kTiles; ++it) {
        if (it + 1 < kTiles) cp_wait1(); else cp_wait0();
        __syncthreads();
        if (it + 2 < kTiles) {
            int nb = buf + 2; if (nb >= NSTAGE) nb -= NSTAGE;
            load_tiles4(smBase, nb, Ah, Al, lda, Bh, Bl, ldb,
                        rowBase, colBase, (it + 2) << 5, tid);
            cp_commit();
        }
        compute_tiles(smBase, buf, wm, wn, lane, acc);
        if (++buf == NSTAGE) buf = 0;
    }
}

// ---------------------------------------------------------------------------
// Stage 0: one merged hi/lo split for x, Wq, Wk, Wv
// ---------------------------------------------------------------------------
__global__ void split_all(const float* __restrict__ x,
                          const float* __restrict__ Wq,
                          const float* __restrict__ Wk,
                          const float* __restrict__ Wv)
{
    const size_t NX4 = (size_t)BB * SS * EE / 4;       // 2M vec4 groups
    const size_t NW4 = (size_t)EE * EE / 4;            // 256K per W
    size_t i4 = (size_t)blockIdx.x * 256 + threadIdx.x;
    const float* src;
    bf16 *dh, *dl;
    size_t off;
    if (i4 < NX4) {
        src = x; dh = g_xh; dl = g_xl; off = i4 * 4;
    } else {
        size_t j = i4 - NX4;
        int w = (int)(j / NW4);
        off = (j - (size_t)w * NW4) * 4;
        src = (w == 0) ? Wq : (w == 1) ? Wk : Wv;
        dh = g_Wh + (size_t)w * EE * EE;
        dl = g_Wl + (size_t)w * EE * EE;
    }
    float4 v = *(const float4*)(src + off);
    bf16 h0 = __float2bfloat16(v.x), h1 = __float2bfloat16(v.y);
    bf16 h2 = __float2bfloat16(v.z), h3 = __float2bfloat16(v.w);
    bf16 l0 = __float2bfloat16(v.x - __bfloat162float(h0));
    bf16 l1 = __float2bfloat16(v.y - __bfloat162float(h1));
    bf16 l2 = __float2bfloat16(v.z - __bfloat162float(h2));
    bf16 l3 = __float2bfloat16(v.w - __bfloat162float(h3));
    *(__nv_bfloat162*)(dh + off)     = __halves2bfloat162(h0, h1);
    *(__nv_bfloat162*)(dh + off + 2) = __halves2bfloat162(h2, h3);
    *(__nv_bfloat162*)(dl + off)     = __halves2bfloat162(l0, l1);
    *(__nv_bfloat162*)(dl + off + 2) = __halves2bfloat162(l2, l3);
}

// ---------------------------------------------------------------------------
// Stage 1: QKV projections. grid (8, 64, 3)
// ---------------------------------------------------------------------------
__global__ void __launch_bounds__(256, 2) qkv_gemm(
    const float* __restrict__ bq, const float* __restrict__ bk,
    const float* __restrict__ bv)
{
    extern __shared__ char smc[];
    unsigned smBase = smem_u32(smc);
    const int tid = threadIdx.x, lane = tid & 31, wid = tid >> 5;
    const int wm = wid & 3, wn = wid >> 2;
    const int z = blockIdx.z;
    const int rowBase = blockIdx.y * 128, colBase = blockIdx.x * 128;

    const bf16* Bh = g_Wh + (size_t)z * EE * EE;
    const bf16* Bl = g_Wl + (size_t)z * EE * EE;
    const float* bias = (z == 0) ? bq : (z == 1) ? bk : bv;
    bf16* oh = (z == 0) ? g_qh : (z == 1) ? g_kh : g_vh;
    bf16* ol = (z == 0) ? g_ql : (z == 1) ? g_kl : g_vl;
    const float alpha = (z == 0) ? 0.03125f : 1.0f;

    float acc[2][8][4] = {};
    gemm_mainloop(g_xh, g_xl, EE, Bh, Bl, EE, EE, rowBase, colBase, smBase, acc);

    #pragma unroll
    for (int mi = 0; mi < 2; mi++)
        #pragma unroll
        for (int ni = 0; ni < 8; ni++) {
            int col = colBase + wn * 64 + ni * 8 + (lane & 3) * 2;
            float b0 = bias[col], b1 = bias[col + 1];
            #pragma unroll
            for (int h = 0; h < 2; h++) {
                int row = rowBase + wm * 32 + mi * 16 + (lane >> 2) + h * 8;
                float y0 = (acc[mi][ni][2 * h]     + b0) * alpha;
                float y1 = (acc[mi][ni][2 * h + 1] + b1) * alpha;
                bf16 h0 = __float2bfloat16(y0), h1 = __float2bfloat16(y1);
                bf16 l0 = __float2bfloat16(y0 - __bfloat162float(h0));
                bf16 l1 = __float2bfloat16(y1 - __bfloat162float(h1));
                size_t off = (size_t)row * EE + col;
                *(__nv_bfloat162*)(oh + off) = __halves2bfloat162(h0, h1);
                *(__nv_bfloat162*)(ol + off) = __halves2bfloat162(l0, l1);
            }
        }
}

// ---------------------------------------------------------------------------
// Stage 2: scores = q_scaled @ k^T. Compact lower-triangular grid (136, 1, 4)
// ---------------------------------------------------------------------------
__global__ void __launch_bounds__(256, 2) scores_gemm()
{
    extern __shared__ char smc[];
    unsigned smBase = smem_u32(smc);
    const int tid = threadIdx.x, lane = tid & 31, wid = tid >> 5;
    const int wm = wid & 3, wn = wid >> 2;
    const int z = blockIdx.z;

    // decode lower-triangular tile index -> (by, bx), bx <= by
    int idx = blockIdx.x;
    int by = (int)((sqrtf(8.0f * idx + 1.0f) - 1.0f) * 0.5f);
    while ((by + 1) * (by + 2) / 2 <= idx) by++;
    while (by * (by + 1) / 2 > idx) by--;
    int bx = idx - by * (by + 1) / 2;

    const int rowBase = by * 128, colBase = bx * 128;

    float acc[2][8][4] = {};
    gemm_mainloop(g_qh + (size_t)z * SS * EE, g_ql + (size_t)z * SS * EE, EE,
                  g_kh + (size_t)z * SS * EE, g_kl + (size_t)z * SS * EE, EE,
                  EE, rowBase, colBase, smBase, acc);

    float* out = g_sc + (size_t)z * SS * SS;
    #pragma unroll
    for (int mi = 0; mi < 2; mi++)
        #pragma unroll
        for (int ni = 0; ni < 8; ni++) {
            int col = colBase + wn * 64 + ni * 8 + (lane & 3) * 2;
            #pragma unroll
            for (int h = 0; h < 2; h++) {
                int row = rowBase + wm * 32 + mi * 16 + (lane >> 2) + h * 8;
                *(float2*)(out + (size_t)row * SS + col) =
                    make_float2(acc[mi][ni][2 * h], acc[mi][ni][2 * h + 1]);
            }
        }
}

// ---------------------------------------------------------------------------
// Stage 2b: per-row softmax stats (max, 1/sumexp). grid B*S
// ---------------------------------------------------------------------------
__global__ void stats_kernel()
{
    const int rowg = blockIdx.x;
    const int b = rowg >> 11;
    const int i = rowg & (SS - 1);
    const float* p = g_sc + (size_t)b * SS * SS + (size_t)i * SS;
    const int L = i + 1;

    __shared__ float red[8], red2[8];
    const int t = threadIdx.x, lane = t & 31, w = t >> 5;

    float m = -1e30f;
    for (int j = t; j < L; j += 256) m = fmaxf(m, p[j]);
    #pragma unroll
    for (int o = 16; o; o >>= 1) m = fmaxf(m, __shfl_xor_sync(~0u, m, o));
    if (lane == 0) red[w] = m;
    __syncthreads();
    m = red[0];
    #pragma unroll
    for (int ww = 1; ww < 8; ww++) m = fmaxf(m, red[ww]);

    float s = 0.0f;
    for (int j = t; j < L; j += 256) s += __expf(p[j] - m);
    #pragma unroll
    for (int o = 16; o; o >>= 1) s += __shfl_xor_sync(~0u, s, o);
    if (lane == 0) red2[w] = s;
    __syncthreads();
    s = red2[0];
    #pragma unroll
    for (int ww = 1; ww < 8; ww++) s += red2[ww];

    if (t == 0) {
        g_m[rowg] = m;
        g_inv[rowg] = 1.0f / s;
    }
}

// ---------------------------------------------------------------------------
// Stage 3: out = P @ vT with fused softmax. grid (8, 16, 4)
// y reversed so long-k CTAs launch first (tail packing).
// ---------------------------------------------------------------------------
__global__ void __launch_bounds__(256, 2) av_gemm(float* __restrict__ gout)
{
    extern __shared__ char smc[];
    unsigned smBase = smem_u32(smc);
    const int tid = threadIdx.x, lane = tid & 31, wid = tid >> 5;
    const int wm = wid & 3, wn = wid >> 2;
    const int z = blockIdx.z;
    const int by = 15 - blockIdx.y;            // long CTAs first
    const int rowBase = by * 128, colBase = blockIdx.x * 128;
    const int kTiles = (by + 1) * 4;

    const bf16* Bh = g_vTh + (size_t)z * EE * SS;
    const bf16* Bl = g_vTl + (size_t)z * EE * SS;
    const float* sc = g_sc + (size_t)z * SS * SS;

    const int r = tid >> 1, ch = (tid & 1) * 16;
    const int grow = rowBase + r;
    const float rm = g_m[z * SS + grow];
    const float rinv = g_inv[z * SS + grow];
    const float* srow = sc + (size_t)grow * SS + ch;

    auto load_B = [&](int buf, int kt) {
        const unsigned dstb = smBase + buf * (4 * TILE_B);
        const char* sBh = (const char*)(Bh + (size_t)colBase * SS + kt);
        const char* sBl = (const char*)(Bl + (size_t)colBase * SS + kt);
        const size_t str = (size_t)SS * 2;
        #pragma unroll
        for (int i = 0; i < 4; i++) {
            const int tile = 2 + (i >> 1);
            int within = tid + (i & 1) * 256;
            int row = within >> 2, c = within & 3;
            const char* src = (tile == 2) ? sBh + row * str + c * 16
                                          : sBl + row * str + c * 16;
            cp16(dstb + tile * TILE_B + SWOFF(row, c), src);
        }
    };
    float4 sreg[4];
    auto ldg_A = [&](int kt) {
        const float* s0 = srow + kt;
        #pragma unroll
        for (int j = 0; j < 4; j++) sreg[j] = *(const float4*)(s0 + j * 4);
    };
    auto sts_A = [&](int buf, int kt) {
        char* base = smc + buf * (4 * TILE_B);
        const int sw = ((r >> 1) & 3);
        #pragma unroll
        for (int j = 0; j < 4; j++) {
            float sv[4] = {sreg[j].x, sreg[j].y, sreg[j].z, sreg[j].w};
            float pv[4];
            #pragma unroll
            for (int e = 0; e < 4; e++) {
                int gcol = kt + ch + j * 4 + e;
                pv[e] = (gcol <= grow) ? __expf(sv[e] - rm) * rinv : 0.0f;
            }
            bf16 h0 = __float2bfloat16(pv[0]), h1 = __float2bfloat16(pv[1]);
            bf16 h2 = __float2bfloat16(pv[2]), h3 = __float2bfloat16(pv[3]);
            bf16 l0 = __float2bfloat16(pv[0] - __bfloat162float(h0));
            bf16 l1 = __float2bfloat16(pv[1] - __bfloat162float(h1));
            bf16 l2 = __float2bfloat16(pv[2] - __bfloat162float(h2));
            bf16 l3 = __float2bfloat16(pv[3] - __bfloat162float(h3));
            int ccb = ch + j * 4;
            int unit = ccb >> 3;
            int boff = r * 64 + ((unit ^ sw) << 4) + (ccb & 7) * 2;
            *(__nv_bfloat162*)(base + 0 * TILE_B + boff)     = __halves2bfloat162(h0, h1);
            *(__nv_bfloat162*)(base + 0 * TILE_B + boff + 4) = __halves2bfloat162(h2, h3);
            *(__nv_bfloat162*)(base + 1 * TILE_B + boff)     = __halves2bfloat162(l0, l1);
            *(__nv_bfloat162*)(base + 1 * TILE_B + boff + 4) = __halves2bfloat162(l2, l3);
        }
    };

    float acc[2][8][4] = {};

    load_B(0, 0);
    cp_commit();
    ldg_A(0);
    if (kTiles > 1) {
        load_B(1, 32);
        cp_commit();
    }

    int buf = 0;
    for (int it = 0; it < kTiles; ++it) {
        sts_A(buf, it << 5);
        if (it + 1 < kTiles) cp_wait1(); else cp_wait0();
        __syncthreads();
        if (it + 2 < kTiles) {
            int nb = buf + 2; if (nb >= NSTAGE) nb -= NSTAGE;
            load_B(nb, (it + 2) << 5);
            cp_commit();
        }
        if (it + 1 < kTiles) ldg_A((it + 1) << 5);
        compute_tiles(smBase, buf, wm, wn, lane, acc);
        if (++buf == NSTAGE) buf = 0;
    }

    float* out = gout + (size_t)z * SS * EE;
    #pragma unroll
    for (int mi = 0; mi < 2; mi++)
        #pragma unroll
        for (int ni = 0; ni < 8; ni++) {
            int col = colBase + wn * 64 + ni * 8 + (lane & 3) * 2;
            #pragma unroll
            for (int h = 0; h < 2; h++) {
                int row = rowBase + wm * 32 + mi * 16 + (lane >> 2) + h * 8;
                *(float2*)(out + (size_t)row * EE + col) =
                    make_float2(acc[mi][ni][2 * h], acc[mi][ni][2 * h + 1]);
            }
        }
}

// ---------------------------------------------------------------------------
// Transpose v (per batch): [S, E] -> [E, S], hi and lo
// ---------------------------------------------------------------------------
__global__ void transpose_v()
{
    __shared__ bf16 th[32][33], tl[32][33];
    const int z = blockIdx.z;
    const int s0 = blockIdx.x * 32, e0 = blockIdx.y * 32;
    const int tx = threadIdx.x, ty = threadIdx.y;
    #pragma unroll
    for (int j = 0; j < 32; j += 8) {
        size_t src = ((size_t)z * SS + s0 + ty + j) * EE + e0 + tx;
        th[ty + j][tx] = g_vh[src];
        tl[ty + j][tx] = g_vl[src];
    }
    __syncthreads();
    #pragma unroll
    for (int j = 0; j < 32; j += 8) {
        size_t dst = ((size_t)z * EE + e0 + ty + j) * SS + s0 + tx;
        g_vTh[dst] = th[tx][ty + j];
        g_vTl[dst] = tl[tx][ty + j];
    }
}

// ---------------------------------------------------------------------------
// Launch
// ---------------------------------------------------------------------------
extern "C" void kernel_launch(void* const* d_in, const int* in_sizes, int n_in,
                              void* d_out, int out_size)
{
    const float* x  = (const float*)d_in[0];
    const float* Wq = (const float*)d_in[2];
    const float* bq = (const float*)d_in[3];
    const float* Wk = (const float*)d_in[4];
    const float* bk = (const float*)d_in[5];
    const float* Wv = (const float*)d_in[6];
    const float* bv = (const float*)d_in[7];
    float* out = (float*)d_out;

    static bool attr_done = false;
    if (!attr_done) {
        cudaFuncSetAttribute(qkv_gemm,    cudaFuncAttributeMaxDynamicSharedMemorySize, SMEM_BYTES);
        cudaFuncSetAttribute(scores_gemm, cudaFuncAttributeMaxDynamicSharedMemorySize, SMEM_BYTES);
        cudaFuncSetAttribute(av_gemm,     cudaFuncAttributeMaxDynamicSharedMemorySize, SMEM_BYTES);
        attr_done = true;
    }

    // 1) merged hi/lo splits: x + Wq + Wk + Wv  (2M + 3*256K vec4 groups)
    const int splitBlocks = (BB * SS * EE / 4 + 3 * (EE * EE / 4)) / 256;
    split_all<<<splitBlocks, 256>>>(x, Wq, Wk, Wv);

    // 2) QKV projections (q pre-scaled by 1/32)
    qkv_gemm<<<dim3(EE / 128, (BB * SS) / 128, 3), 256, SMEM_BYTES>>>(bq, bk, bv);

    // 3) transpose v
    transpose_v<<<dim3(SS / 32, EE / 32, BB), dim3(32, 8)>>>();

    // 4) scores — compact lower-triangular grid
    scores_gemm<<<dim3(136, 1, BB), 256, SMEM_BYTES>>>();

    // 5) per-row softmax stats
    stats_kernel<<<BB * SS, 256>>>();

    // 6) fused softmax + P @ vT (reversed-y scheduling)
    av_gemm<<<dim3(EE / 128, SS / 128, BB), 256, SMEM_BYTES>>>(out);
}

// round 8
// speedup vs baseline: 1.2113x; 1.0007x over previous
#include <cuda_runtime.h>
#include <cuda_bf16.h>

#define BB 4
#define SS 2048
#define EE 1024

typedef __nv_bfloat16 bf16;

// ---------------------------------------------------------------------------
// Scratch (device globals — no allocation allowed)
// ---------------------------------------------------------------------------
__device__ float g_sc[(size_t)BB * SS * SS];
__device__ float g_m[BB * SS], g_inv[BB * SS];
__device__ bf16 g_xh[(size_t)BB * SS * EE], g_xl[(size_t)BB * SS * EE];
__device__ bf16 g_Wh[3 * (size_t)EE * EE], g_Wl[3 * (size_t)EE * EE];
__device__ bf16 g_qh[(size_t)BB * SS * EE], g_ql[(size_t)BB * SS * EE];
__device__ bf16 g_kh[(size_t)BB * SS * EE], g_kl[(size_t)BB * SS * EE];
__device__ bf16 g_vh[(size_t)BB * SS * EE], g_vl[(size_t)BB * SS * EE];
__device__ bf16 g_vTh[(size_t)BB * EE * SS], g_vTl[(size_t)BB * EE * SS];

// ---------------------------------------------------------------------------
// PTX helpers (baseline sm_80+ features only — plain sm_103 target)
// ---------------------------------------------------------------------------
__device__ __forceinline__ unsigned smem_u32(const void* p) {
    unsigned a;
    asm("{ .reg .u64 t; cvta.to.shared.u64 t, %1; cvt.u32.u64 %0, t; }"
        : "=r"(a) : "l"(p));
    return a;
}
__device__ __forceinline__ void cp16(unsigned dst, const void* src) {
    asm volatile("cp.async.cg.shared.global [%0], [%1], 16;"
                 :: "r"(dst), "l"(src) : "memory");
}
__device__ __forceinline__ void cp_commit() {
    asm volatile("cp.async.commit_group;" ::: "memory");
}
__device__ __forceinline__ void cp_wait1() {
    asm volatile("cp.async.wait_group 1;" ::: "memory");
}
__device__ __forceinline__ void cp_wait0() {
    asm volatile("cp.async.wait_group 0;" ::: "memory");
}
__device__ __forceinline__ void ldsm4(unsigned& r0, unsigned& r1, unsigned& r2,
                                      unsigned& r3, unsigned addr) {
    asm volatile("ldmatrix.sync.aligned.m8n8.x4.shared.b16 {%0,%1,%2,%3}, [%4];"
                 : "=r"(r0), "=r"(r1), "=r"(r2), "=r"(r3) : "r"(addr));
}
__device__ __forceinline__ void mma16816(float* d, const unsigned* a,
                                         unsigned b0, unsigned b1) {
    asm volatile(
        "mma.sync.aligned.m16n8k16.row.col.f32.bf16.bf16.f32 "
        "{%0,%1,%2,%3}, {%4,%5,%6,%7}, {%8,%9}, {%0,%1,%2,%3};"
        : "+f"(d[0]), "+f"(d[1]), "+f"(d[2]), "+f"(d[3])
        : "r"(a[0]), "r"(a[1]), "r"(a[2]), "r"(a[3]), "r"(b0), "r"(b1));
}

// ---------------------------------------------------------------------------
// Tile layout: 128 rows x 32 bf16 = 64B rows, XOR-swizzled 16B units.
// Per stage: 4 tiles [Ah, Al, Bh, Bl]. 3 stages = 96KB -> 2 CTAs/SM.
// ---------------------------------------------------------------------------
#define TILE_B 8192
#define NSTAGE 3
#define SMEM_BYTES (NSTAGE * 4 * TILE_B)    // 98304
#define SWOFF(row, c) ((row) * 64 + (((c) ^ (((row) >> 1) & 3)) << 4))

// 3-pass compute, pass-major MMA order: same accumulator revisited only after
// 16 independent MMAs -> HMMA accumulate latency fully hidden.
__device__ __forceinline__ void compute_tiles(unsigned smBase, int buf,
                                              int wm, int wn, int lane,
                                              float acc[2][8][4])
{
    const unsigned tb = smBase + buf * (4 * TILE_B);
    const int lrow = lane & 15;
    const int lcu = lane >> 4;
    // hoisted per-fragment swizzled offsets (row part constant across ks)
    #pragma unroll
    for (int ks = 0; ks < 2; ks++) {
        const int cu = ks * 2 + lcu;
        unsigned ah[2][4], al[2][4], bh[4][4], bl[4][4];
        #pragma unroll
        for (int mi = 0; mi < 2; mi++) {
            int row = wm * 32 + mi * 16 + lrow;
            unsigned off = SWOFF(row, cu);
            ldsm4(ah[mi][0], ah[mi][1], ah[mi][2], ah[mi][3], tb + 0 * TILE_B + off);
            ldsm4(al[mi][0], al[mi][1], al[mi][2], al[mi][3], tb + 1 * TILE_B + off);
        }
        #pragma unroll
        for (int nj = 0; nj < 4; nj++) {
            int row = wn * 64 + nj * 16 + lrow;
            unsigned off = SWOFF(row, cu);
            ldsm4(bh[nj][0], bh[nj][1], bh[nj][2], bh[nj][3], tb + 2 * TILE_B + off);
            ldsm4(bl[nj][0], bl[nj][1], bl[nj][2], bl[nj][3], tb + 3 * TILE_B + off);
        }
        // pass 1: Ah * Bh
        #pragma unroll
        for (int mi = 0; mi < 2; mi++)
            #pragma unroll
            for (int nj = 0; nj < 4; nj++) {
                mma16816(acc[mi][2 * nj],     ah[mi], bh[nj][0], bh[nj][2]);
                mma16816(acc[mi][2 * nj + 1], ah[mi], bh[nj][1], bh[nj][3]);
            }
        // pass 2: Al * Bh
        #pragma unroll
        for (int mi = 0; mi < 2; mi++)
            #pragma unroll
            for (int nj = 0; nj < 4; nj++) {
                mma16816(acc[mi][2 * nj],     al[mi], bh[nj][0], bh[nj][2]);
                mma16816(acc[mi][2 * nj + 1], al[mi], bh[nj][1], bh[nj][3]);
            }
        // pass 3: Ah * Bl
        #pragma unroll
        for (int mi = 0; mi < 2; mi++)
            #pragma unroll
            for (int nj = 0; nj < 4; nj++) {
                mma16816(acc[mi][2 * nj],     ah[mi], bl[nj][0], bl[nj][2]);
                mma16816(acc[mi][2 * nj + 1], ah[mi], bl[nj][1], bl[nj][3]);
            }
    }
}

// cp.async loader for all 4 bf16 tiles (swizzled dst)
__device__ __forceinline__ void load_tiles4(unsigned smBase, int buf,
    const bf16* Ah, const bf16* Al, int lda,
    const bf16* Bh, const bf16* Bl, int ldb,
    int rowBase, int colBase, int kt, int tid)
{
    const unsigned dstb = smBase + buf * (4 * TILE_B);
    const char* srcA_h = (const char*)(Ah + (size_t)rowBase * lda + kt);
    const char* srcA_l = (const char*)(Al + (size_t)rowBase * lda + kt);
    const char* srcB_h = (const char*)(Bh + (size_t)colBase * ldb + kt);
    const char* srcB_l = (const char*)(Bl + (size_t)colBase * ldb + kt);
    const size_t strA = (size_t)lda * 2, strB = (size_t)ldb * 2;
    #pragma unroll
    for (int i = 0; i < 8; i++) {
        const int tile = i >> 1;
        int within = tid + (i & 1) * 256;
        int row = within >> 2, c = within & 3;
        const char* src = (tile == 0) ? srcA_h + row * strA + c * 16
                        : (tile == 1) ? srcA_l + row * strA + c * 16
                        : (tile == 2) ? srcB_h + row * strB + c * 16
                                      : srcB_l + row * strB + c * 16;
        cp16(dstb + tile * TILE_B + SWOFF(row, c), src);
    }
}

// Full bf16 GEMM mainloop: 3-stage pipeline, ONE barrier per k-iter
__device__ __forceinline__ void gemm_mainloop(
    const bf16* __restrict__ Ah, const bf16* __restrict__ Al, int lda,
    const bf16* __restrict__ Bh, const bf16* __restrict__ Bl, int ldb,
    int kEnd, int rowBase, int colBase, unsigned smBase, float acc[2][8][4])
{
    const int tid = threadIdx.x;
    const int lane = tid & 31, wid = tid >> 5;
    const int wm = wid & 3, wn = wid >> 2;
    const int kTiles = kEnd >> 5;

    load_tiles4(smBase, 0, Ah, Al, lda, Bh, Bl, ldb, rowBase, colBase, 0, tid);
    cp_commit();
    if (kTiles > 1) {
        load_tiles4(smBase, 1, Ah, Al, lda, Bh, Bl, ldb, rowBase, colBase, 32, tid);
        cp_commit();
    }

    int buf = 0;
    for (int it = 0; it < kTiles; ++it) {
        if (it + 1 < kTiles) cp_wait1(); else cp_wait0();
        __syncthreads();
        if (it + 2 < kTiles) {
            int nb = buf + 2; if (nb >= NSTAGE) nb -= NSTAGE;
            load_tiles4(smBase, nb, Ah, Al, lda, Bh, Bl, ldb,
                        rowBase, colBase, (it + 2) << 5, tid);
            cp_commit();
        }
        compute_tiles(smBase, buf, wm, wn, lane, acc);
        if (++buf == NSTAGE) buf = 0;
    }
}

// ---------------------------------------------------------------------------
// Stage 0: one merged hi/lo split for x, Wq, Wk, Wv
// ---------------------------------------------------------------------------
__global__ void split_all(const float* __restrict__ x,
                          const float* __restrict__ Wq,
                          const float* __restrict__ Wk,
                          const float* __restrict__ Wv)
{
    const size_t NX4 = (size_t)BB * SS * EE / 4;
    const size_t NW4 = (size_t)EE * EE / 4;
    size_t i4 = (size_t)blockIdx.x * 256 + threadIdx.x;
    const float* src;
    bf16 *dh, *dl;
    size_t off;
    if (i4 < NX4) {
        src = x; dh = g_xh; dl = g_xl; off = i4 * 4;
    } else {
        size_t j = i4 - NX4;
        int w = (int)(j / NW4);
        off = (j - (size_t)w * NW4) * 4;
        src = (w == 0) ? Wq : (w == 1) ? Wk : Wv;
        dh = g_Wh + (size_t)w * EE * EE;
        dl = g_Wl + (size_t)w * EE * EE;
    }
    float4 v = *(const float4*)(src + off);
    bf16 h0 = __float2bfloat16(v.x), h1 = __float2bfloat16(v.y);
    bf16 h2 = __float2bfloat16(v.z), h3 = __float2bfloat16(v.w);
    bf16 l0 = __float2bfloat16(v.x - __bfloat162float(h0));
    bf16 l1 = __float2bfloat16(v.y - __bfloat162float(h1));
    bf16 l2 = __float2bfloat16(v.z - __bfloat162float(h2));
    bf16 l3 = __float2bfloat16(v.w - __bfloat162float(h3));
    *(__nv_bfloat162*)(dh + off)     = __halves2bfloat162(h0, h1);
    *(__nv_bfloat162*)(dh + off + 2) = __halves2bfloat162(h2, h3);
    *(__nv_bfloat162*)(dl + off)     = __halves2bfloat162(l0, l1);
    *(__nv_bfloat162*)(dl + off + 2) = __halves2bfloat162(l2, l3);
}

// ---------------------------------------------------------------------------
// Stage 1: QKV projections. grid (8, 64, 3)
// ---------------------------------------------------------------------------
__global__ void __launch_bounds__(256, 2) qkv_gemm(
    const float* __restrict__ bq, const float* __restrict__ bk,
    const float* __restrict__ bv)
{
    extern __shared__ char smc[];
    unsigned smBase = smem_u32(smc);
    const int tid = threadIdx.x, lane = tid & 31, wid = tid >> 5;
    const int wm = wid & 3, wn = wid >> 2;
    const int z = blockIdx.z;
    const int rowBase = blockIdx.y * 128, colBase = blockIdx.x * 128;

    const bf16* Bh = g_Wh + (size_t)z * EE * EE;
    const bf16* Bl = g_Wl + (size_t)z * EE * EE;
    const float* bias = (z == 0) ? bq : (z == 1) ? bk : bv;
    bf16* oh = (z == 0) ? g_qh : (z == 1) ? g_kh : g_vh;
    bf16* ol = (z == 0) ? g_ql : (z == 1) ? g_kl : g_vl;
    const float alpha = (z == 0) ? 0.03125f : 1.0f;

    float acc[2][8][4] = {};
    gemm_mainloop(g_xh, g_xl, EE, Bh, Bl, EE, EE, rowBase, colBase, smBase, acc);

    #pragma unroll
    for (int mi = 0; mi < 2; mi++)
        #pragma unroll
        for (int ni = 0; ni < 8; ni++) {
            int col = colBase + wn * 64 + ni * 8 + (lane & 3) * 2;
            float b0 = bias[col], b1 = bias[col + 1];
            #pragma unroll
            for (int h = 0; h < 2; h++) {
                int row = rowBase + wm * 32 + mi * 16 + (lane >> 2) + h * 8;
                float y0 = (acc[mi][ni][2 * h]     + b0) * alpha;
                float y1 = (acc[mi][ni][2 * h + 1] + b1) * alpha;
                bf16 h0 = __float2bfloat16(y0), h1 = __float2bfloat16(y1);
                bf16 l0 = __float2bfloat16(y0 - __bfloat162float(h0));
                bf16 l1 = __float2bfloat16(y1 - __bfloat162float(h1));
                size_t off = (size_t)row * EE + col;
                *(__nv_bfloat162*)(oh + off) = __halves2bfloat162(h0, h1);
                *(__nv_bfloat162*)(ol + off) = __halves2bfloat162(l0, l1);
            }
        }
}

// ---------------------------------------------------------------------------
// Stage 2: scores = q_scaled @ k^T. Compact lower-triangular grid (136, 1, 4)
// ---------------------------------------------------------------------------
__global__ void __launch_bounds__(256, 2) scores_gemm()
{
    extern __shared__ char smc[];
    unsigned smBase = smem_u32(smc);
    const int tid = threadIdx.x, lane = tid & 31, wid = tid >> 5;
    const int wm = wid & 3, wn = wid >> 2;
    const int z = blockIdx.z;

    int idx = blockIdx.x;
    int by = (int)((sqrtf(8.0f * idx + 1.0f) - 1.0f) * 0.5f);
    while ((by + 1) * (by + 2) / 2 <= idx) by++;
    while (by * (by + 1) / 2 > idx) by--;
    int bx = idx - by * (by + 1) / 2;

    const int rowBase = by * 128, colBase = bx * 128;

    float acc[2][8][4] = {};
    gemm_mainloop(g_qh + (size_t)z * SS * EE, g_ql + (size_t)z * SS * EE, EE,
                  g_kh + (size_t)z * SS * EE, g_kl + (size_t)z * SS * EE, EE,
                  EE, rowBase, colBase, smBase, acc);

    float* out = g_sc + (size_t)z * SS * SS;
    #pragma unroll
    for (int mi = 0; mi < 2; mi++)
        #pragma unroll
        for (int ni = 0; ni < 8; ni++) {
            int col = colBase + wn * 64 + ni * 8 + (lane & 3) * 2;
            #pragma unroll
            for (int h = 0; h < 2; h++) {
                int row = rowBase + wm * 32 + mi * 16 + (lane >> 2) + h * 8;
                *(float2*)(out + (size_t)row * SS + col) =
                    make_float2(acc[mi][ni][2 * h], acc[mi][ni][2 * h + 1]);
            }
        }
}

// ---------------------------------------------------------------------------
// Stage 2b: per-row softmax stats (max, 1/sumexp). grid B*S
// ---------------------------------------------------------------------------
__global__ void stats_kernel()
{
    const int rowg = blockIdx.x;
    const int b = rowg >> 11;
    const int i = rowg & (SS - 1);
    const float* p = g_sc + (size_t)b * SS * SS + (size_t)i * SS;
    const int L = i + 1;

    __shared__ float red[8], red2[8];
    const int t = threadIdx.x, lane = t & 31, w = t >> 5;

    float m = -1e30f;
    for (int j = t; j < L; j += 256) m = fmaxf(m, p[j]);
    #pragma unroll
    for (int o = 16; o; o >>= 1) m = fmaxf(m, __shfl_xor_sync(~0u, m, o));
    if (lane == 0) red[w] = m;
    __syncthreads();
    m = red[0];
    #pragma unroll
    for (int ww = 1; ww < 8; ww++) m = fmaxf(m, red[ww]);

    float s = 0.0f;
    for (int j = t; j < L; j += 256) s += __expf(p[j] - m);
    #pragma unroll
    for (int o = 16; o; o >>= 1) s += __shfl_xor_sync(~0u, s, o);
    if (lane == 0) red2[w] = s;
    __syncthreads();
    s = red2[0];
    #pragma unroll
    for (int ww = 1; ww < 8; ww++) s += red2[ww];

    if (t == 0) {
        g_m[rowg] = m;
        g_inv[rowg] = 1.0f / s;
    }
}

// ---------------------------------------------------------------------------
// Stage 3: out = P @ vT with fused softmax. grid (8, 16, 4)
// ---------------------------------------------------------------------------
__global__ void __launch_bounds__(256, 2) av_gemm(float* __restrict__ gout)
{
    extern __shared__ char smc[];
    unsigned smBase = smem_u32(smc);
    const int tid = threadIdx.x, lane = tid & 31, wid = tid >> 5;
    const int wm = wid & 3, wn = wid >> 2;
    const int z = blockIdx.z;
    const int by = 15 - blockIdx.y;            // long CTAs first
    const int rowBase = by * 128, colBase = blockIdx.x * 128;
    const int kTiles = (by + 1) * 4;

    const bf16* Bh = g_vTh + (size_t)z * EE * SS;
    const bf16* Bl = g_vTl + (size_t)z * EE * SS;
    const float* sc = g_sc + (size_t)z * SS * SS;

    const int r = tid >> 1, ch = (tid & 1) * 16;
    const int grow = rowBase + r;
    const float rm = g_m[z * SS + grow];
    const float rinv = g_inv[z * SS + grow];
    const float* srow = sc + (size_t)grow * SS + ch;

    auto load_B = [&](int buf, int kt) {
        const unsigned dstb = smBase + buf * (4 * TILE_B);
        const char* sBh = (const char*)(Bh + (size_t)colBase * SS + kt);
        const char* sBl = (const char*)(Bl + (size_t)colBase * SS + kt);
        const size_t str = (size_t)SS * 2;
        #pragma unroll
        for (int i = 0; i < 4; i++) {
            const int tile = 2 + (i >> 1);
            int within = tid + (i & 1) * 256;
            int row = within >> 2, c = within & 3;
            const char* src = (tile == 2) ? sBh + row * str + c * 16
                                          : sBl + row * str + c * 16;
            cp16(dstb + tile * TILE_B + SWOFF(row, c), src);
        }
    };
    float4 sreg[4];
    auto ldg_A = [&](int kt) {
        const float* s0 = srow + kt;
        #pragma unroll
        for (int j = 0; j < 4; j++) sreg[j] = *(const float4*)(s0 + j * 4);
    };
    auto sts_A = [&](int buf, int kt) {
        char* base = smc + buf * (4 * TILE_B);
        const int sw = ((r >> 1) & 3);
        #pragma unroll
        for (int j = 0; j < 4; j++) {
            float sv[4] = {sreg[j].x, sreg[j].y, sreg[j].z, sreg[j].w};
            float pv[4];
            #pragma unroll
            for (int e = 0; e < 4; e++) {
                int gcol = kt + ch + j * 4 + e;
                pv[e] = (gcol <= grow) ? __expf(sv[e] - rm) * rinv : 0.0f;
            }
            bf16 h0 = __float2bfloat16(pv[0]), h1 = __float2bfloat16(pv[1]);
            bf16 h2 = __float2bfloat16(pv[2]), h3 = __float2bfloat16(pv[3]);
            bf16 l0 = __float2bfloat16(pv[0] - __bfloat162float(h0));
            bf16 l1 = __float2bfloat16(pv[1] - __bfloat162float(h1));
            bf16 l2 = __float2bfloat16(pv[2] - __bfloat162float(h2));
            bf16 l3 = __float2bfloat16(pv[3] - __bfloat162float(h3));
            int ccb = ch + j * 4;
            int unit = ccb >> 3;
            int boff = r * 64 + ((unit ^ sw) << 4) + (ccb & 7) * 2;
            *(__nv_bfloat162*)(base + 0 * TILE_B + boff)     = __halves2bfloat162(h0, h1);
            *(__nv_bfloat162*)(base + 0 * TILE_B + boff + 4) = __halves2bfloat162(h2, h3);
            *(__nv_bfloat162*)(base + 1 * TILE_B + boff)     = __halves2bfloat162(l0, l1);
            *(__nv_bfloat162*)(base + 1 * TILE_B + boff + 4) = __halves2bfloat162(l2, l3);
        }
    };

    float acc[2][8][4] = {};

    load_B(0, 0);
    cp_commit();
    ldg_A(0);
    if (kTiles > 1) {
        load_B(1, 32);
        cp_commit();
    }

    int buf = 0;
    for (int it = 0; it < kTiles; ++it) {
        sts_A(buf, it << 5);
        if (it + 1 < kTiles) cp_wait1(); else cp_wait0();
        __syncthreads();
        if (it + 2 < kTiles) {
            int nb = buf + 2; if (nb >= NSTAGE) nb -= NSTAGE;
            load_B(nb, (it + 2) << 5);
            cp_commit();
        }
        if (it + 1 < kTiles) ldg_A((it + 1) << 5);
        compute_tiles(smBase, buf, wm, wn, lane, acc);
        if (++buf == NSTAGE) buf = 0;
    }

    float* out = gout + (size_t)z * SS * EE;
    #pragma unroll
    for (int mi = 0; mi < 2; mi++)
        #pragma unroll
        for (int ni = 0; ni < 8; ni++) {
            int col = colBase + wn * 64 + ni * 8 + (lane & 3) * 2;
            #pragma unroll
            for (int h = 0; h < 2; h++) {
                int row = rowBase + wm * 32 + mi * 16 + (lane >> 2) + h * 8;
                *(float2*)(out + (size_t)row * EE + col) =
                    make_float2(acc[mi][ni][2 * h], acc[mi][ni][2 * h + 1]);
            }
        }
}

// ---------------------------------------------------------------------------
// Transpose v (per batch): [S, E] -> [E, S], hi and lo
// ---------------------------------------------------------------------------
__global__ void transpose_v()
{
    __shared__ bf16 th[32][33], tl[32][33];
    const int z = blockIdx.z;
    const int s0 = blockIdx.x * 32, e0 = blockIdx.y * 32;
    const int tx = threadIdx.x, ty = threadIdx.y;
    #pragma unroll
    for (int j = 0; j < 32; j += 8) {
        size_t src = ((size_t)z * SS + s0 + ty + j) * EE + e0 + tx;
        th[ty + j][tx] = g_vh[src];
        tl[ty + j][tx] = g_vl[src];
    }
    __syncthreads();
    #pragma unroll
    for (int j = 0; j < 32; j += 8) {
        size_t dst = ((size_t)z * EE + e0 + ty + j) * SS + s0 + tx;
        g_vTh[dst] = th[tx][ty + j];
        g_vTl[dst] = tl[tx][ty + j];
    }
}

// ---------------------------------------------------------------------------
// Launch
// ---------------------------------------------------------------------------
extern "C" void kernel_launch(void* const* d_in, const int* in_sizes, int n_in,
                              void* d_out, int out_size)
{
    const float* x  = (const float*)d_in[0];
    const float* Wq = (const float*)d_in[2];
    const float* bq = (const float*)d_in[3];
    const float* Wk = (const float*)d_in[4];
    const float* bk = (const float*)d_in[5];
    const float* Wv = (const float*)d_in[6];
    const float* bv = (const float*)d_in[7];
    float* out = (float*)d_out;

    static bool attr_done = false;
    if (!attr_done) {
        cudaFuncSetAttribute(qkv_gemm,    cudaFuncAttributeMaxDynamicSharedMemorySize, SMEM_BYTES);
        cudaFuncSetAttribute(scores_gemm, cudaFuncAttributeMaxDynamicSharedMemorySize, SMEM_BYTES);
        cudaFuncSetAttribute(av_gemm,     cudaFuncAttributeMaxDynamicSharedMemorySize, SMEM_BYTES);
        attr_done = true;
    }

    const int splitBlocks = (BB * SS * EE / 4 + 3 * (EE * EE / 4)) / 256;
    split_all<<<splitBlocks, 256>>>(x, Wq, Wk, Wv);

    qkv_gemm<<<dim3(EE / 128, (BB * SS) / 128, 3), 256, SMEM_BYTES>>>(bq, bk, bv);

    transpose_v<<<dim3(SS / 32, EE / 32, BB), dim3(32, 8)>>>();

    scores_gemm<<<dim3(136, 1, BB), 256, SMEM_BYTES>>>();

    stats_kernel<<<BB * SS, 256>>>();

    av_gemm<<<dim3(EE / 128, SS / 128, BB), 256, SMEM_BYTES>>>(out);
}